// round 1
// baseline (speedup 1.0000x reference)
#include <cuda_runtime.h>
#include <math.h>

#define N_NODES 100000
#define N_EDGES 1600000
#define D 128
#define BN_EPS 1e-5f

// ---------------- scratch (allocation-free: __device__ globals) ----------------
__device__ float  g_agg1[(size_t)N_NODES * D];   // 51.2 MB  sum_{src->dst} x[src]
__device__ float  g_deg [N_NODES];               // in-degree (float)
__device__ float  g_hpre[(size_t)N_NODES * D];   // 51.2 MB  pre-BN layer-1 output
__device__ float  g_p   [N_NODES * 2];           // h1 @ W2l
__device__ float  g_r   [N_NODES * 2];           // h1 @ W2r
__device__ float  g_agg2[N_NODES * 2];           // sum of p over edges
__device__ float  g_opre[N_NODES * 2];           // pre-BN layer-2 output
__device__ double g_s1[D], g_q1[D];              // BN1 col sum / sumsq
__device__ double g_s2[2], g_q2[2];              // BN2 col sum / sumsq
__device__ float  g_scale1[D], g_shift1[D];      // folded BN1 affine
__device__ int    g_is64;                        // edge_index dtype flag

// ---------------- dtype detection ----------------
__global__ void k_detect(const int* __restrict__ ei) {
    __shared__ int any_nonzero;
    if (threadIdx.x == 0) any_nonzero = 0;
    __syncthreads();
    // If int64: words at odd positions are high words of values < 100000 -> all 0.
    // If int32: odd positions are real random indices -> ~never all 0 (256 checks).
    int v = ei[2 * threadIdx.x + 1];
    if (v != 0) atomicOr(&any_nonzero, 1);
    __syncthreads();
    if (threadIdx.x == 0) g_is64 = (any_nonzero == 0) ? 1 : 0;
}

// ---------------- zero scratch ----------------
__global__ void k_zero() {
    long long i = (long long)blockIdx.x * blockDim.x + threadIdx.x;
    long long stride = (long long)gridDim.x * blockDim.x;
    float4 z4 = make_float4(0.f, 0.f, 0.f, 0.f);
    for (long long j = i; j < (long long)N_NODES * D / 4; j += stride)
        ((float4*)g_agg1)[j] = z4;
    for (long long j = i; j < N_NODES; j += stride) g_deg[j] = 0.f;
    for (long long j = i; j < N_NODES * 2; j += stride) g_agg2[j] = 0.f;
    if (i < D)   { g_s1[i] = 0.0; g_q1[i] = 0.0; }
    if (i < 2)   { g_s2[i] = 0.0; g_q2[i] = 0.0; }
}

// ---------------- layer-1 edge aggregation: warp per edge ----------------
__global__ void k_edge1(const float* __restrict__ x, const void* __restrict__ eiv) {
    long long gi = (long long)blockIdx.x * blockDim.x + threadIdx.x;
    int e    = (int)(gi >> 5);
    int lane = threadIdx.x & 31;
    if (e >= N_EDGES) return;
    long long s, d;
    if (g_is64) {
        const long long* E = (const long long*)eiv;
        s = E[e]; d = E[N_EDGES + e];
    } else {
        const int* E = (const int*)eiv;
        s = E[e]; d = E[N_EDGES + e];
    }
    float4 v = *((const float4*)(x + s * D) + lane);
    float* dp = g_agg1 + d * D + lane * 4;
    asm volatile("red.global.add.v4.f32 [%0], {%1,%2,%3,%4};"
                 :: "l"(dp), "f"(v.x), "f"(v.y), "f"(v.z), "f"(v.w) : "memory");
    if (lane == 0) atomicAdd(g_deg + d, 1.0f);
}

// ---------------- layer-1 fused SGEMM: hpre = [mean, x] @ [W1l; W1r] + b1 ----
// M=100000, K=256 (two 128 halves), N=128. BM=128, BN=128, BK=16, 256 thr, 8x8 micro
__global__ void __launch_bounds__(256) k_gemm1(
    const float* __restrict__ x, const float* __restrict__ W1l,
    const float* __restrict__ W1r, const float* __restrict__ b1) {
    __shared__ float As[16 * 128];   // [k][m]
    __shared__ float Bs[16 * 128];   // [k][n]
    __shared__ float sinv[128];
    const int tid = threadIdx.x;
    const int m0  = blockIdx.x * 128;
    if (tid < 128) {
        int m = m0 + tid;
        float dg = (m < N_NODES) ? g_deg[m] : 1.0f;
        sinv[tid] = 1.0f / fmaxf(dg, 1.0f);
    }
    __syncthreads();

    float acc[8][8];
    #pragma unroll
    for (int i = 0; i < 8; i++)
        #pragma unroll
        for (int j = 0; j < 8; j++) acc[i][j] = 0.f;

    const int ty = tid >> 4;   // 0..15
    const int tx = tid & 15;   // 0..15

    for (int kt = 0; kt < 16; ++kt) {
        const int  k0    = kt * 16;
        const bool first = (k0 < 128);
        const float* Ab = first ? (g_agg1 + k0) : (x + (k0 - 128));
        const float* Bb = first ? (W1l + k0 * 128) : (W1r + (k0 - 128) * 128);

        // A tile: 128 rows x 16 cols -> As[k][m], scale first half by 1/deg
        #pragma unroll
        for (int i = 0; i < 2; i++) {
            int idx = tid + i * 256;
            int r   = idx >> 2;      // 0..127
            int c4  = idx & 3;       // 0..3 (float4 within 16-wide k slice)
            int m   = m0 + r;
            float4 v = make_float4(0.f, 0.f, 0.f, 0.f);
            if (m < N_NODES) v = *(const float4*)(Ab + (long long)m * D + c4 * 4);
            float sc = first ? sinv[r] : 1.0f;
            As[(c4 * 4 + 0) * 128 + r] = v.x * sc;
            As[(c4 * 4 + 1) * 128 + r] = v.y * sc;
            As[(c4 * 4 + 2) * 128 + r] = v.z * sc;
            As[(c4 * 4 + 3) * 128 + r] = v.w * sc;
        }
        // B tile: 16 rows x 128 cols
        #pragma unroll
        for (int i = 0; i < 2; i++) {
            int idx = tid + i * 256;
            int r   = idx >> 5;      // 0..15
            int c   = idx & 31;      // float4 col
            *(float4*)(Bs + r * 128 + c * 4) = *(const float4*)(Bb + r * 128 + c * 4);
        }
        __syncthreads();

        #pragma unroll
        for (int kk = 0; kk < 16; kk++) {
            float a[8], b[8];
            *(float4*)(a)     = *(const float4*)(As + kk * 128 + ty * 8);
            *(float4*)(a + 4) = *(const float4*)(As + kk * 128 + ty * 8 + 4);
            *(float4*)(b)     = *(const float4*)(Bs + kk * 128 + tx * 8);
            *(float4*)(b + 4) = *(const float4*)(Bs + kk * 128 + tx * 8 + 4);
            #pragma unroll
            for (int i = 0; i < 8; i++)
                #pragma unroll
                for (int j = 0; j < 8; j++)
                    acc[i][j] = fmaf(a[i], b[j], acc[i][j]);
        }
        __syncthreads();
    }

    // epilogue: + b1, store
    float bb[8];
    *(float4*)(bb)     = *(const float4*)(b1 + tx * 8);
    *(float4*)(bb + 4) = *(const float4*)(b1 + tx * 8 + 4);
    #pragma unroll
    for (int i = 0; i < 8; i++) {
        int m = m0 + ty * 8 + i;
        if (m < N_NODES) {
            float4 v0, v1;
            v0.x = acc[i][0] + bb[0]; v0.y = acc[i][1] + bb[1];
            v0.z = acc[i][2] + bb[2]; v0.w = acc[i][3] + bb[3];
            v1.x = acc[i][4] + bb[4]; v1.y = acc[i][5] + bb[5];
            v1.z = acc[i][6] + bb[6]; v1.w = acc[i][7] + bb[7];
            *(float4*)(g_hpre + (long long)m * D + tx * 8)     = v0;
            *(float4*)(g_hpre + (long long)m * D + tx * 8 + 4) = v1;
        }
    }
}

// ---------------- BN1 column stats ----------------
__global__ void k_stats1() {
    int c = threadIdx.x;            // 128 threads, one per column
    float s = 0.f, q = 0.f;
    for (int r = blockIdx.x; r < N_NODES; r += gridDim.x) {
        float v = g_hpre[(long long)r * D + c];
        s += v; q += v * v;
    }
    atomicAdd(&g_s1[c], (double)s);
    atomicAdd(&g_q1[c], (double)q);
}

__global__ void k_bnparams1(const float* __restrict__ gamma1,
                            const float* __restrict__ beta1) {
    int c = threadIdx.x;
    double mu  = g_s1[c] / (double)N_NODES;
    double var = g_q1[c] / (double)N_NODES - mu * mu;
    double sc  = (double)gamma1[c] / sqrt(var + (double)BN_EPS);
    g_scale1[c] = (float)sc;
    g_shift1[c] = (float)((double)beta1[c] - mu * sc);
}

// ---------------- BN1 + ReLU + project to 2 dims (warp per node) -------------
__global__ void k_proj(const float* __restrict__ W2l, const float* __restrict__ W2r) {
    long long gi = (long long)blockIdx.x * blockDim.x + threadIdx.x;
    int n    = (int)(gi >> 5);
    int lane = threadIdx.x & 31;
    if (n >= N_NODES) return;
    float4 h = *(const float4*)(g_hpre + (long long)n * D + lane * 4);
    float hv[4] = {h.x, h.y, h.z, h.w};
    float p0 = 0.f, p1 = 0.f, r0 = 0.f, r1 = 0.f;
    #pragma unroll
    for (int j = 0; j < 4; j++) {
        int c = lane * 4 + j;
        float v = fmaxf(fmaf(hv[j], g_scale1[c], g_shift1[c]), 0.f);
        p0 = fmaf(v, W2l[2 * c],     p0);
        p1 = fmaf(v, W2l[2 * c + 1], p1);
        r0 = fmaf(v, W2r[2 * c],     r0);
        r1 = fmaf(v, W2r[2 * c + 1], r1);
    }
    #pragma unroll
    for (int o = 16; o; o >>= 1) {
        p0 += __shfl_xor_sync(0xffffffffu, p0, o);
        p1 += __shfl_xor_sync(0xffffffffu, p1, o);
        r0 += __shfl_xor_sync(0xffffffffu, r0, o);
        r1 += __shfl_xor_sync(0xffffffffu, r1, o);
    }
    if (lane == 0) {
        *(float2*)(g_p + 2 * n) = make_float2(p0, p1);
        *(float2*)(g_r + 2 * n) = make_float2(r0, r1);
    }
}

// ---------------- layer-2 edge aggregation (2-dim, thread per edge) ----------
__global__ void k_edge2(const void* __restrict__ eiv) {
    int e = blockIdx.x * blockDim.x + threadIdx.x;
    if (e >= N_EDGES) return;
    long long s, d;
    if (g_is64) {
        const long long* E = (const long long*)eiv;
        s = E[e]; d = E[N_EDGES + e];
    } else {
        const int* E = (const int*)eiv;
        s = E[e]; d = E[N_EDGES + e];
    }
    float2 v = *(const float2*)(g_p + 2 * s);
    float* dp = g_agg2 + 2 * d;
    asm volatile("red.global.add.v2.f32 [%0], {%1,%2};"
                 :: "l"(dp), "f"(v.x), "f"(v.y) : "memory");
}

// ---------------- layer-2 pre-BN output + BN2 stats ----------------
__global__ void k_outpre(const float* __restrict__ b2) {
    int i = blockIdx.x * blockDim.x + threadIdx.x;
    float o0 = 0.f, o1 = 0.f;
    if (i < N_NODES) {
        float inv = 1.0f / fmaxf(g_deg[i], 1.0f);
        float2 a = *(const float2*)(g_agg2 + 2 * i);
        float2 r = *(const float2*)(g_r + 2 * i);
        o0 = fmaf(a.x, inv, b2[0] + r.x);
        o1 = fmaf(a.y, inv, b2[1] + r.y);
        *(float2*)(g_opre + 2 * i) = make_float2(o0, o1);
    }
    float q0 = o0 * o0, q1 = o1 * o1;
    #pragma unroll
    for (int o = 16; o; o >>= 1) {
        o0 += __shfl_xor_sync(0xffffffffu, o0, o);
        o1 += __shfl_xor_sync(0xffffffffu, o1, o);
        q0 += __shfl_xor_sync(0xffffffffu, q0, o);
        q1 += __shfl_xor_sync(0xffffffffu, q1, o);
    }
    __shared__ float sh[4][8];
    int w = threadIdx.x >> 5, l = threadIdx.x & 31;
    if (l == 0) { sh[0][w] = o0; sh[1][w] = o1; sh[2][w] = q0; sh[3][w] = q1; }
    __syncthreads();
    if (threadIdx.x == 0) {
        float s0 = 0.f, s1 = 0.f, t0 = 0.f, t1 = 0.f;
        #pragma unroll
        for (int k = 0; k < 8; k++) { s0 += sh[0][k]; s1 += sh[1][k]; t0 += sh[2][k]; t1 += sh[3][k]; }
        atomicAdd(&g_s2[0], (double)s0);
        atomicAdd(&g_s2[1], (double)s1);
        atomicAdd(&g_q2[0], (double)t0);
        atomicAdd(&g_q2[1], (double)t1);
    }
}

// ---------------- BN2 + log_softmax ----------------
__global__ void k_final(const float* __restrict__ gamma2, const float* __restrict__ beta2,
                        float* __restrict__ out) {
    int i = blockIdx.x * blockDim.x + threadIdx.x;
    if (i >= N_NODES) return;
    double mu0 = g_s2[0] / (double)N_NODES;
    double mu1 = g_s2[1] / (double)N_NODES;
    double v0  = g_q2[0] / (double)N_NODES - mu0 * mu0;
    double v1  = g_q2[1] / (double)N_NODES - mu1 * mu1;
    float sc0 = (float)((double)gamma2[0] / sqrt(v0 + (double)BN_EPS));
    float sc1 = (float)((double)gamma2[1] / sqrt(v1 + (double)BN_EPS));
    float sh0 = (float)((double)beta2[0] - mu0 * sc0);
    float sh1 = (float)((double)beta2[1] - mu1 * sc1);
    float2 o = *(const float2*)(g_opre + 2 * i);
    float a = fmaf(o.x, sc0, sh0);
    float b = fmaf(o.y, sc1, sh1);
    float m = fmaxf(a, b);
    float lse = m + logf(expf(a - m) + expf(b - m));
    *(float2*)(out + 2 * i) = make_float2(a - lse, b - lse);
}

// ---------------- launch ----------------
extern "C" void kernel_launch(void* const* d_in, const int* in_sizes, int n_in,
                              void* d_out, int out_size) {
    const float* x    = (const float*)d_in[0];
    const void*  ei   = d_in[1];
    const float* W1l  = (const float*)d_in[2];
    const float* b1   = (const float*)d_in[3];
    const float* W1r  = (const float*)d_in[4];
    const float* g1   = (const float*)d_in[5];
    const float* be1  = (const float*)d_in[6];
    const float* W2l  = (const float*)d_in[7];
    const float* b2   = (const float*)d_in[8];
    const float* W2r  = (const float*)d_in[9];
    const float* g2   = (const float*)d_in[10];
    const float* be2  = (const float*)d_in[11];
    float* out = (float*)d_out;

    k_detect<<<1, 256>>>((const int*)ei);
    k_zero<<<1024, 256>>>();
    k_edge1<<<(N_EDGES * 32 + 255) / 256, 256>>>(x, ei);
    k_gemm1<<<(N_NODES + 127) / 128, 256>>>(x, W1l, W1r, b1);
    k_stats1<<<800, 128>>>();
    k_bnparams1<<<1, 128>>>(g1, be1);
    k_proj<<<(N_NODES * 32 + 255) / 256, 256>>>(W2l, W2r);
    k_edge2<<<(N_EDGES + 255) / 256, 256>>>(ei);
    k_outpre<<<(N_NODES + 255) / 256, 256>>>(b2);
    k_final<<<(N_NODES + 255) / 256, 256>>>(g2, be2, out);
}

// round 2
// speedup vs baseline: 1.4320x; 1.4320x over previous
#include <cuda_runtime.h>
#include <math.h>

#define N_NODES 100000
#define N_EDGES 1600000
#define D 128
#define BN_EPS 1e-5f
#define SCAN_BLK 1024
#define N_SCAN_BLKS ((N_NODES + SCAN_BLK - 1) / SCAN_BLK)   // 98

// ---------------- scratch (allocation-free: __device__ globals) ----------------
__device__ float  g_mean[(size_t)N_NODES * D];   // 51.2 MB  mean_{src->dst} x[src]
__device__ float  g_inv [N_NODES];               // 1/max(deg,1)
__device__ float  g_hpre[(size_t)N_NODES * D];   // 51.2 MB  pre-BN layer-1 output
__device__ float  g_p   [N_NODES * 2];           // h1 @ W2l
__device__ float  g_r   [N_NODES * 2];           // h1 @ W2r
__device__ float  g_opre[N_NODES * 2];           // pre-BN layer-2 output
__device__ double g_s1[D], g_q1[D];              // BN1 col sum / sumsq
__device__ double g_s2[2], g_q2[2];              // BN2 col sum / sumsq
__device__ float  g_scale1[D], g_shift1[D];      // folded BN1 affine
__device__ int    g_is64;                        // edge_index dtype flag
// CSR build
__device__ int    g_cnt[N_NODES];
__device__ int    g_rowtmp[N_NODES];
__device__ int    g_rowstart[N_NODES + 1];
__device__ int    g_cur[N_NODES];
__device__ int    g_partial[N_SCAN_BLKS];
__device__ int    g_csr[N_EDGES];

// ---------------- dtype detection ----------------
__global__ void k_detect(const int* __restrict__ ei) {
    __shared__ int any_nonzero;
    if (threadIdx.x == 0) any_nonzero = 0;
    __syncthreads();
    // int64 values < 100000 => every high word is 0. int32 random indices at odd
    // positions => essentially never all zero over 256 samples.
    int v = ei[2 * threadIdx.x + 1];
    if (v != 0) atomicOr(&any_nonzero, 1);
    __syncthreads();
    if (threadIdx.x == 0) g_is64 = (any_nonzero == 0) ? 1 : 0;
}

// ---------------- zero small scratch ----------------
__global__ void k_zero() {
    int i = blockIdx.x * blockDim.x + threadIdx.x;
    int stride = gridDim.x * blockDim.x;
    for (int j = i; j < N_NODES; j += stride) g_cnt[j] = 0;
    if (i < D) { g_s1[i] = 0.0; g_q1[i] = 0.0; }
    if (i < 2) { g_s2[i] = 0.0; g_q2[i] = 0.0; }
}

// ---------------- CSR build ----------------
__global__ void k_hist(const int* __restrict__ ei) {
    int e = blockIdx.x * blockDim.x + threadIdx.x;
    if (e >= N_EDGES) return;
    int d = g_is64 ? ei[2 * (N_EDGES + e)] : ei[N_EDGES + e];
    atomicAdd(&g_cnt[d], 1);
}

__global__ void k_scan1() {
    __shared__ int sh[SCAN_BLK];
    int tid = threadIdx.x;
    int i = blockIdx.x * SCAN_BLK + tid;
    int v = (i < N_NODES) ? g_cnt[i] : 0;
    sh[tid] = v;
    __syncthreads();
    #pragma unroll
    for (int off = 1; off < SCAN_BLK; off <<= 1) {
        int t = (tid >= off) ? sh[tid - off] : 0;
        __syncthreads();
        sh[tid] += t;
        __syncthreads();
    }
    if (i < N_NODES) g_rowtmp[i] = sh[tid] - v;     // exclusive
    if (tid == SCAN_BLK - 1) g_partial[blockIdx.x] = sh[tid];
}

__global__ void k_scan2() {
    __shared__ int sh[N_SCAN_BLKS];
    int tid = threadIdx.x;
    if (tid < N_SCAN_BLKS) sh[tid] = g_partial[tid];
    __syncthreads();
    if (tid == 0) {
        int run = 0;
        for (int b = 0; b < N_SCAN_BLKS; b++) { int t = sh[b]; sh[b] = run; run += t; }
    }
    __syncthreads();
    if (tid < N_SCAN_BLKS) g_partial[tid] = sh[tid];
}

__global__ void k_scan3() {
    int i = blockIdx.x * blockDim.x + threadIdx.x;
    if (i < N_NODES) {
        int v = g_rowtmp[i] + g_partial[i / SCAN_BLK];
        g_rowstart[i] = v;
        g_cur[i] = v;
    }
    if (i == 0) g_rowstart[N_NODES] = N_EDGES;
}

__global__ void k_scatter(const int* __restrict__ ei) {
    int e = blockIdx.x * blockDim.x + threadIdx.x;
    if (e >= N_EDGES) return;
    int s, d;
    if (g_is64) { s = ei[2 * e]; d = ei[2 * (N_EDGES + e)]; }
    else        { s = ei[e];     d = ei[N_EDGES + e]; }
    int pos = atomicAdd(&g_cur[d], 1);
    g_csr[pos] = s;
}

// ---------------- mean aggregation: warp per node, no atomics ----------------
__global__ void k_agg(const float* __restrict__ x) {
    int gi = blockIdx.x * blockDim.x + threadIdx.x;
    int n = gi >> 5;
    int lane = threadIdx.x & 31;
    if (n >= N_NODES) return;
    int beg = g_rowstart[n], end = g_rowstart[n + 1];
    float4 acc = make_float4(0.f, 0.f, 0.f, 0.f);
    for (int base = beg; base < end; base += 32) {
        int cnt = min(32, end - base);
        int sid = (base + lane < end) ? __ldg(g_csr + base + lane) : 0;
        for (int j = 0; j < cnt; j++) {
            int s = __shfl_sync(0xffffffffu, sid, j);
            float4 v = __ldg((const float4*)(x + (size_t)s * D) + lane);
            acc.x += v.x; acc.y += v.y; acc.z += v.z; acc.w += v.w;
        }
    }
    float inv = 1.0f / fmaxf((float)(end - beg), 1.0f);
    acc.x *= inv; acc.y *= inv; acc.z *= inv; acc.w *= inv;
    *((float4*)(g_mean + (size_t)n * D) + lane) = acc;
    if (lane == 0) g_inv[n] = inv;
}

// ---------------- layer-1 fused SGEMM: hpre = [mean, x] @ [W1l; W1r] + b1 ----
// fused BN1 column stats in the epilogue
__global__ void __launch_bounds__(256) k_gemm1(
    const float* __restrict__ x, const float* __restrict__ W1l,
    const float* __restrict__ W1r, const float* __restrict__ b1) {
    __shared__ float As[16 * 128];   // [k][m]
    __shared__ float Bs[16 * 128];   // [k][n]
    __shared__ float s_sum[128], s_sq[128];
    const int tid = threadIdx.x;
    const int m0  = blockIdx.x * 128;
    if (tid < 128) { s_sum[tid] = 0.f; s_sq[tid] = 0.f; }

    float acc[8][8];
    #pragma unroll
    for (int i = 0; i < 8; i++)
        #pragma unroll
        for (int j = 0; j < 8; j++) acc[i][j] = 0.f;

    const int ty = tid >> 4;   // 0..15
    const int tx = tid & 15;   // 0..15

    for (int kt = 0; kt < 16; ++kt) {
        const int  k0    = kt * 16;
        const bool first = (k0 < 128);
        const float* Ab = first ? (g_mean + k0) : (x + (k0 - 128));
        const float* Bb = first ? (W1l + k0 * 128) : (W1r + (k0 - 128) * 128);

        #pragma unroll
        for (int i = 0; i < 2; i++) {
            int idx = tid + i * 256;
            int r   = idx >> 2;
            int c4  = idx & 3;
            int m   = m0 + r;
            float4 v = make_float4(0.f, 0.f, 0.f, 0.f);
            if (m < N_NODES) v = *(const float4*)(Ab + (size_t)m * D + c4 * 4);
            As[(c4 * 4 + 0) * 128 + r] = v.x;
            As[(c4 * 4 + 1) * 128 + r] = v.y;
            As[(c4 * 4 + 2) * 128 + r] = v.z;
            As[(c4 * 4 + 3) * 128 + r] = v.w;
        }
        #pragma unroll
        for (int i = 0; i < 2; i++) {
            int idx = tid + i * 256;
            int r   = idx >> 5;
            int c   = idx & 31;
            *(float4*)(Bs + r * 128 + c * 4) = *(const float4*)(Bb + r * 128 + c * 4);
        }
        __syncthreads();

        #pragma unroll
        for (int kk = 0; kk < 16; kk++) {
            float a[8], b[8];
            *(float4*)(a)     = *(const float4*)(As + kk * 128 + ty * 8);
            *(float4*)(a + 4) = *(const float4*)(As + kk * 128 + ty * 8 + 4);
            *(float4*)(b)     = *(const float4*)(Bs + kk * 128 + tx * 8);
            *(float4*)(b + 4) = *(const float4*)(Bs + kk * 128 + tx * 8 + 4);
            #pragma unroll
            for (int i = 0; i < 8; i++)
                #pragma unroll
                for (int j = 0; j < 8; j++)
                    acc[i][j] = fmaf(a[i], b[j], acc[i][j]);
        }
        __syncthreads();
    }

    // epilogue: + b1, store, accumulate BN1 stats
    float bb[8];
    *(float4*)(bb)     = *(const float4*)(b1 + tx * 8);
    *(float4*)(bb + 4) = *(const float4*)(b1 + tx * 8 + 4);
    float csum[8], csq[8];
    #pragma unroll
    for (int j = 0; j < 8; j++) { csum[j] = 0.f; csq[j] = 0.f; }
    #pragma unroll
    for (int i = 0; i < 8; i++) {
        int m = m0 + ty * 8 + i;
        if (m < N_NODES) {
            float v[8];
            #pragma unroll
            for (int j = 0; j < 8; j++) {
                v[j] = acc[i][j] + bb[j];
                csum[j] += v[j];
                csq[j]  += v[j] * v[j];
            }
            *(float4*)(g_hpre + (size_t)m * D + tx * 8)     = *(float4*)(v);
            *(float4*)(g_hpre + (size_t)m * D + tx * 8 + 4) = *(float4*)(v + 4);
        }
    }
    #pragma unroll
    for (int j = 0; j < 8; j++) {
        atomicAdd(&s_sum[tx * 8 + j], csum[j]);
        atomicAdd(&s_sq[tx * 8 + j],  csq[j]);
    }
    __syncthreads();
    if (tid < 128) {
        atomicAdd(&g_s1[tid], (double)s_sum[tid]);
        atomicAdd(&g_q1[tid], (double)s_sq[tid]);
    }
}

__global__ void k_bnparams1(const float* __restrict__ gamma1,
                            const float* __restrict__ beta1) {
    int c = threadIdx.x;
    double mu  = g_s1[c] / (double)N_NODES;
    double var = g_q1[c] / (double)N_NODES - mu * mu;
    double sc  = (double)gamma1[c] / sqrt(var + (double)BN_EPS);
    g_scale1[c] = (float)sc;
    g_shift1[c] = (float)((double)beta1[c] - mu * sc);
}

// ---------------- BN1 + ReLU + project to 2 dims (warp per node) -------------
__global__ void k_proj(const float* __restrict__ W2l, const float* __restrict__ W2r) {
    int gi = blockIdx.x * blockDim.x + threadIdx.x;
    int n    = gi >> 5;
    int lane = threadIdx.x & 31;
    if (n >= N_NODES) return;
    float4 h = *(const float4*)(g_hpre + (size_t)n * D + lane * 4);
    float hv[4] = {h.x, h.y, h.z, h.w};
    float p0 = 0.f, p1 = 0.f, r0 = 0.f, r1 = 0.f;
    #pragma unroll
    for (int j = 0; j < 4; j++) {
        int c = lane * 4 + j;
        float v = fmaxf(fmaf(hv[j], g_scale1[c], g_shift1[c]), 0.f);
        p0 = fmaf(v, W2l[2 * c],     p0);
        p1 = fmaf(v, W2l[2 * c + 1], p1);
        r0 = fmaf(v, W2r[2 * c],     r0);
        r1 = fmaf(v, W2r[2 * c + 1], r1);
    }
    #pragma unroll
    for (int o = 16; o; o >>= 1) {
        p0 += __shfl_xor_sync(0xffffffffu, p0, o);
        p1 += __shfl_xor_sync(0xffffffffu, p1, o);
        r0 += __shfl_xor_sync(0xffffffffu, r0, o);
        r1 += __shfl_xor_sync(0xffffffffu, r1, o);
    }
    if (lane == 0) {
        *(float2*)(g_p + 2 * n) = make_float2(p0, p1);
        *(float2*)(g_r + 2 * n) = make_float2(r0, r1);
    }
}

// ---------------- layer 2: CSR gather + outpre + BN2 stats (fused) ----------
__global__ void k_l2(const float* __restrict__ b2) {
    int i = blockIdx.x * blockDim.x + threadIdx.x;
    float o0 = 0.f, o1 = 0.f;
    if (i < N_NODES) {
        int beg = g_rowstart[i], end = g_rowstart[i + 1];
        float s0 = 0.f, s1 = 0.f;
        for (int e = beg; e < end; e++) {
            int sidx = __ldg(g_csr + e);
            float2 v = *(const float2*)(g_p + 2 * sidx);
            s0 += v.x; s1 += v.y;
        }
        float inv = g_inv[i];
        float2 r = *(const float2*)(g_r + 2 * i);
        o0 = fmaf(s0, inv, b2[0] + r.x);
        o1 = fmaf(s1, inv, b2[1] + r.y);
        *(float2*)(g_opre + 2 * i) = make_float2(o0, o1);
    }
    float q0 = o0 * o0, q1 = o1 * o1;
    #pragma unroll
    for (int o = 16; o; o >>= 1) {
        o0 += __shfl_xor_sync(0xffffffffu, o0, o);
        o1 += __shfl_xor_sync(0xffffffffu, o1, o);
        q0 += __shfl_xor_sync(0xffffffffu, q0, o);
        q1 += __shfl_xor_sync(0xffffffffu, q1, o);
    }
    __shared__ float sh[4][8];
    int w = threadIdx.x >> 5, l = threadIdx.x & 31;
    if (l == 0) { sh[0][w] = o0; sh[1][w] = o1; sh[2][w] = q0; sh[3][w] = q1; }
    __syncthreads();
    if (threadIdx.x == 0) {
        float s0 = 0.f, s1 = 0.f, t0 = 0.f, t1 = 0.f;
        #pragma unroll
        for (int k = 0; k < 8; k++) { s0 += sh[0][k]; s1 += sh[1][k]; t0 += sh[2][k]; t1 += sh[3][k]; }
        atomicAdd(&g_s2[0], (double)s0);
        atomicAdd(&g_s2[1], (double)s1);
        atomicAdd(&g_q2[0], (double)t0);
        atomicAdd(&g_q2[1], (double)t1);
    }
}

// ---------------- BN2 + log_softmax ----------------
__global__ void k_final(const float* __restrict__ gamma2, const float* __restrict__ beta2,
                        float* __restrict__ out) {
    int i = blockIdx.x * blockDim.x + threadIdx.x;
    if (i >= N_NODES) return;
    double mu0 = g_s2[0] / (double)N_NODES;
    double mu1 = g_s2[1] / (double)N_NODES;
    double v0  = g_q2[0] / (double)N_NODES - mu0 * mu0;
    double v1  = g_q2[1] / (double)N_NODES - mu1 * mu1;
    float sc0 = (float)((double)gamma2[0] / sqrt(v0 + (double)BN_EPS));
    float sc1 = (float)((double)gamma2[1] / sqrt(v1 + (double)BN_EPS));
    float sh0 = (float)((double)beta2[0] - mu0 * sc0);
    float sh1 = (float)((double)beta2[1] - mu1 * sc1);
    float2 o = *(const float2*)(g_opre + 2 * i);
    float a = fmaf(o.x, sc0, sh0);
    float b = fmaf(o.y, sc1, sh1);
    float m = fmaxf(a, b);
    float lse = m + logf(expf(a - m) + expf(b - m));
    *(float2*)(out + 2 * i) = make_float2(a - lse, b - lse);
}

// ---------------- launch ----------------
extern "C" void kernel_launch(void* const* d_in, const int* in_sizes, int n_in,
                              void* d_out, int out_size) {
    const float* x    = (const float*)d_in[0];
    const int*   ei   = (const int*)d_in[1];
    const float* W1l  = (const float*)d_in[2];
    const float* b1   = (const float*)d_in[3];
    const float* W1r  = (const float*)d_in[4];
    const float* g1   = (const float*)d_in[5];
    const float* be1  = (const float*)d_in[6];
    const float* W2l  = (const float*)d_in[7];
    const float* b2   = (const float*)d_in[8];
    const float* W2r  = (const float*)d_in[9];
    const float* g2   = (const float*)d_in[10];
    const float* be2  = (const float*)d_in[11];
    float* out = (float*)d_out;

    k_detect<<<1, 256>>>(ei);
    k_zero<<<200, 256>>>();
    k_hist<<<(N_EDGES + 255) / 256, 256>>>(ei);
    k_scan1<<<N_SCAN_BLKS, SCAN_BLK>>>();
    k_scan2<<<1, 128>>>();
    k_scan3<<<(N_NODES + 255) / 256, 256>>>();
    k_scatter<<<(N_EDGES + 255) / 256, 256>>>(ei);
    k_agg<<<(N_NODES * 32 + 255) / 256, 256>>>(x);
    k_gemm1<<<(N_NODES + 127) / 128, 256>>>(x, W1l, W1r, b1);
    k_bnparams1<<<1, 128>>>(g1, be1);
    k_proj<<<(N_NODES * 32 + 255) / 256, 256>>>(W2l, W2r);
    k_l2<<<(N_NODES + 255) / 256, 256>>>(b2);
    k_final<<<(N_NODES + 255) / 256, 256>>>(g2, be2, out);
}

// round 4
// speedup vs baseline: 1.7349x; 1.2115x over previous
#include <cuda_runtime.h>
#include <cuda_bf16.h>
#include <math.h>
#include <stdint.h>

#define N_NODES 100000
#define N_EDGES 1600000
#define D 128
#define BN_EPS 1e-5f
#define SCAN_BLK 1024
#define N_SCAN_BLKS ((N_NODES + SCAN_BLK - 1) / SCAN_BLK)   // 98

// ---------------- scratch (allocation-free: __device__ globals) ----------------
__device__ float  g_mean[(size_t)N_NODES * D];   // 51.2 MB  mean_{src->dst} x[src]
__device__ float  g_inv [N_NODES];               // 1/max(deg,1)
__device__ float  g_hpre[(size_t)N_NODES * D];   // 51.2 MB  pre-BN layer-1 output
__device__ float  g_p   [N_NODES * 2];           // h1 @ W2l
__device__ float  g_r   [N_NODES * 2];           // h1 @ W2r
__device__ float  g_opre[N_NODES * 2];           // pre-BN layer-2 output
__device__ double g_s1[D], g_q1[D];              // BN1 col sum / sumsq
__device__ double g_s2[2], g_q2[2];              // BN2 col sum / sumsq
__device__ float  g_scale1[D], g_shift1[D];      // folded BN1 affine
__device__ int    g_is64;                        // edge_index dtype flag
// transposed + bf16-split weights: [n=128][k=256], k = [W1l rows; W1r rows]
__device__ __align__(16) __nv_bfloat16 g_wt_h[128 * 256];
__device__ __align__(16) __nv_bfloat16 g_wt_l[128 * 256];
// CSR build
__device__ int    g_cnt[N_NODES];
__device__ int    g_rowtmp[N_NODES];
__device__ int    g_rowstart[N_NODES + 1];
__device__ int    g_cur[N_NODES];
__device__ int    g_partial[N_SCAN_BLKS];
__device__ int    g_csr[N_EDGES];

// ---------------- helpers ----------------
__device__ __forceinline__ uint32_t smem_u32(const void* p) {
    uint32_t a;
    asm("{ .reg .u64 t; cvta.to.shared.u64 t, %1; cvt.u32.u64 %0, t; }" : "=r"(a) : "l"(p));
    return a;
}
__device__ __forceinline__ void bf16_split2(float x0, float x1, uint32_t& hi, uint32_t& lo) {
    __nv_bfloat16 h0 = __float2bfloat16(x0), h1 = __float2bfloat16(x1);
    __nv_bfloat162 hp = __halves2bfloat162(h0, h1);
    __nv_bfloat162 lp = __halves2bfloat162(
        __float2bfloat16(x0 - __bfloat162float(h0)),
        __float2bfloat16(x1 - __bfloat162float(h1)));
    hi = *(uint32_t*)&hp;
    lo = *(uint32_t*)&lp;
}
#define LDSM4(r, addr) \
    asm volatile("ldmatrix.sync.aligned.m8n8.x4.shared.b16 {%0,%1,%2,%3}, [%4];" \
        : "=r"((r)[0]), "=r"((r)[1]), "=r"((r)[2]), "=r"((r)[3]) : "r"(addr))
#define MMA16816(c, a, b0, b1) \
    asm volatile("mma.sync.aligned.m16n8k16.row.col.f32.bf16.bf16.f32 " \
        "{%0,%1,%2,%3}, {%4,%5,%6,%7}, {%8,%9}, {%0,%1,%2,%3};" \
        : "+f"((c)[0]), "+f"((c)[1]), "+f"((c)[2]), "+f"((c)[3]) \
        : "r"((a)[0]), "r"((a)[1]), "r"((a)[2]), "r"((a)[3]), "r"(b0), "r"(b1))

// ---------------- dtype detection ----------------
__global__ void k_detect(const int* __restrict__ ei) {
    __shared__ int any_nonzero;
    if (threadIdx.x == 0) any_nonzero = 0;
    __syncthreads();
    int v = ei[2 * threadIdx.x + 1];
    if (v != 0) atomicOr(&any_nonzero, 1);
    __syncthreads();
    if (threadIdx.x == 0) g_is64 = (any_nonzero == 0) ? 1 : 0;
}

// ---------------- zero small scratch ----------------
__global__ void k_zero() {
    int i = blockIdx.x * blockDim.x + threadIdx.x;
    int stride = gridDim.x * blockDim.x;
    for (int j = i; j < N_NODES; j += stride) g_cnt[j] = 0;
    if (i < D) { g_s1[i] = 0.0; g_q1[i] = 0.0; }
    if (i < 2) { g_s2[i] = 0.0; g_q2[i] = 0.0; }
}

// ---------------- W -> transposed bf16 hi/lo split ----------------
__global__ void k_wconv(const float* __restrict__ W1l, const float* __restrict__ W1r) {
    int i = blockIdx.x * blockDim.x + threadIdx.x;   // 32768 total
    if (i >= 128 * 256) return;
    int n = i >> 8, k = i & 255;
    float w = (k < 128) ? __ldg(W1l + k * 128 + n) : __ldg(W1r + (k - 128) * 128 + n);
    __nv_bfloat16 h = __float2bfloat16(w);
    g_wt_h[n * 256 + k] = h;
    g_wt_l[n * 256 + k] = __float2bfloat16(w - __bfloat162float(h));
}

// ---------------- CSR build ----------------
__global__ void k_hist(const int* __restrict__ ei) {
    int e = blockIdx.x * blockDim.x + threadIdx.x;
    if (e >= N_EDGES) return;
    int d = g_is64 ? ei[2 * (N_EDGES + e)] : ei[N_EDGES + e];
    atomicAdd(&g_cnt[d], 1);
}

__global__ void k_scan1() {
    __shared__ int sh[SCAN_BLK];
    int tid = threadIdx.x;
    int i = blockIdx.x * SCAN_BLK + tid;
    int v = (i < N_NODES) ? g_cnt[i] : 0;
    sh[tid] = v;
    __syncthreads();
    #pragma unroll
    for (int off = 1; off < SCAN_BLK; off <<= 1) {
        int t = (tid >= off) ? sh[tid - off] : 0;
        __syncthreads();
        sh[tid] += t;
        __syncthreads();
    }
    if (i < N_NODES) g_rowtmp[i] = sh[tid] - v;
    if (tid == SCAN_BLK - 1) g_partial[blockIdx.x] = sh[tid];
}

__global__ void k_scan2() {
    __shared__ int sh[N_SCAN_BLKS];
    int tid = threadIdx.x;
    if (tid < N_SCAN_BLKS) sh[tid] = g_partial[tid];
    __syncthreads();
    if (tid == 0) {
        int run = 0;
        for (int b = 0; b < N_SCAN_BLKS; b++) { int t = sh[b]; sh[b] = run; run += t; }
    }
    __syncthreads();
    if (tid < N_SCAN_BLKS) g_partial[tid] = sh[tid];
}

__global__ void k_scan3() {
    int i = blockIdx.x * blockDim.x + threadIdx.x;
    if (i < N_NODES) {
        int v = g_rowtmp[i] + g_partial[i / SCAN_BLK];
        g_rowstart[i] = v;
        g_cur[i] = v;
    }
    if (i == 0) g_rowstart[N_NODES] = N_EDGES;
}

__global__ void k_scatter(const int* __restrict__ ei) {
    int e = blockIdx.x * blockDim.x + threadIdx.x;
    if (e >= N_EDGES) return;
    int s, d;
    if (g_is64) { s = ei[2 * e]; d = ei[2 * (N_EDGES + e)]; }
    else        { s = ei[e];     d = ei[N_EDGES + e]; }
    int pos = atomicAdd(&g_cur[d], 1);
    g_csr[pos] = s;
}

// ---------------- mean aggregation: warp per node, no atomics ----------------
__global__ void k_agg(const float* __restrict__ x) {
    int gi = blockIdx.x * blockDim.x + threadIdx.x;
    int n = gi >> 5;
    int lane = threadIdx.x & 31;
    if (n >= N_NODES) return;
    int beg = g_rowstart[n], end = g_rowstart[n + 1];
    float4 acc = make_float4(0.f, 0.f, 0.f, 0.f);
    for (int base = beg; base < end; base += 32) {
        int cnt = min(32, end - base);
        int sid = (base + lane < end) ? __ldg(g_csr + base + lane) : 0;
        for (int j = 0; j < cnt; j++) {
            int s = __shfl_sync(0xffffffffu, sid, j);
            float4 v = __ldg((const float4*)(x + (size_t)s * D) + lane);
            acc.x += v.x; acc.y += v.y; acc.z += v.z; acc.w += v.w;
        }
    }
    float inv = 1.0f / fmaxf((float)(end - beg), 1.0f);
    acc.x *= inv; acc.y *= inv; acc.z *= inv; acc.w *= inv;
    *((float4*)(g_mean + (size_t)n * D) + lane) = acc;
    if (lane == 0) g_inv[n] = inv;
}

// ---------------- layer-1 GEMM: HMMA split-bf16 ------------------------------
// hpre[m,n] = sum_k A[m,k] * W[k,n], A = [mean | x] (M=100000, K=256), N=128
// block 128x128, BK=32, 256 thr (8 warps, 2x4), warp tile 64x32 (m16n8k16)
#define BK 32
#define LDA 40   // smem row stride in bf16 (32 + 8 pad)

__global__ void __launch_bounds__(256) k_gemm1(
    const float* __restrict__ x, const float* __restrict__ b1) {
    __shared__ __align__(16) __nv_bfloat16 As_h[128 * LDA];
    __shared__ __align__(16) __nv_bfloat16 As_l[128 * LDA];
    __shared__ __align__(16) __nv_bfloat16 Bs_h[128 * LDA];
    __shared__ __align__(16) __nv_bfloat16 Bs_l[128 * LDA];
    __shared__ float ssum[128], ssq[128];

    const int tid = threadIdx.x;
    const int wid = tid >> 5, l = tid & 31;
    const int warp_m = wid >> 2, warp_n = wid & 3;
    const int m0 = blockIdx.x * 128;
    if (tid < 128) { ssum[tid] = 0.f; ssq[tid] = 0.f; }

    const uint32_t sAh = smem_u32(As_h), sAl = smem_u32(As_l);
    const uint32_t sBh = smem_u32(Bs_h), sBl = smem_u32(Bs_l);

    float acc[4][4][4];
    #pragma unroll
    for (int i = 0; i < 4; i++)
        #pragma unroll
        for (int j = 0; j < 4; j++)
            #pragma unroll
            for (int c = 0; c < 4; c++) acc[i][j][c] = 0.f;

    // staging indices
    const int st_r  = tid >> 1;          // 0..127
    const int st_kh = (tid & 1) * 16;    // 0 / 16

    for (int kc = 0; kc < 256; kc += BK) {
        // ---- stage A: 128 rows x 32 k, fp32 -> bf16 hi/lo ----
        const float* srcbase = (kc < 128) ? (g_mean + kc) : (x + (kc - 128));
        {
            int m = m0 + st_r;
            float4 f[4];
            if (m < N_NODES) {
                const float4* rp = (const float4*)(srcbase + (size_t)m * D) + (st_kh >> 2);
                #pragma unroll
                for (int q = 0; q < 4; q++) f[q] = __ldg(rp + q);
            } else {
                #pragma unroll
                for (int q = 0; q < 4; q++) f[q] = make_float4(0.f, 0.f, 0.f, 0.f);
            }
            uint32_t* dh = (uint32_t*)(As_h + st_r * LDA + st_kh);
            uint32_t* dl = (uint32_t*)(As_l + st_r * LDA + st_kh);
            #pragma unroll
            for (int q = 0; q < 4; q++) {
                uint32_t h0, l0, h1, l1;
                bf16_split2(f[q].x, f[q].y, h0, l0);
                bf16_split2(f[q].z, f[q].w, h1, l1);
                dh[q * 2] = h0; dh[q * 2 + 1] = h1;
                dl[q * 2] = l0; dl[q * 2 + 1] = l1;
            }
        }
        // ---- stage B: 128 n x 32 k from pre-split transposed weights ----
        {
            const uint4* shv = (const uint4*)(g_wt_h + st_r * 256 + kc + st_kh);
            const uint4* slv = (const uint4*)(g_wt_l + st_r * 256 + kc + st_kh);
            uint4* dh = (uint4*)(Bs_h + st_r * LDA + st_kh);
            uint4* dl = (uint4*)(Bs_l + st_r * LDA + st_kh);
            dh[0] = shv[0]; dh[1] = shv[1];
            dl[0] = slv[0]; dl[1] = slv[1];
        }
        __syncthreads();

        #pragma unroll
        for (int kk = 0; kk < 2; kk++) {
            uint32_t ah[4][4], al[4][4], bhf[2][4], blf[2][4];
            #pragma unroll
            for (int mt = 0; mt < 4; mt++) {
                uint32_t off = (uint32_t)(((warp_m * 64 + mt * 16 + (l & 15)) * LDA
                                           + kk * 16 + (l >> 4) * 8) * 2);
                LDSM4(ah[mt], sAh + off);
                LDSM4(al[mt], sAl + off);
            }
            #pragma unroll
            for (int p = 0; p < 2; p++) {
                uint32_t off = (uint32_t)(((warp_n * 32 + p * 16 + (l >> 4) * 8 + (l & 7)) * LDA
                                           + kk * 16 + ((l >> 3) & 1) * 8) * 2);
                LDSM4(bhf[p], sBh + off);
                LDSM4(blf[p], sBl + off);
            }
            #pragma unroll
            for (int mt = 0; mt < 4; mt++)
                #pragma unroll
                for (int nt = 0; nt < 4; nt++) {
                    const int p = nt >> 1, q = nt & 1;
                    MMA16816(acc[mt][nt], ah[mt], bhf[p][2 * q], bhf[p][2 * q + 1]);
                    MMA16816(acc[mt][nt], ah[mt], blf[p][2 * q], blf[p][2 * q + 1]);
                    MMA16816(acc[mt][nt], al[mt], bhf[p][2 * q], bhf[p][2 * q + 1]);
                }
        }
        __syncthreads();
    }

    // ---- epilogue: + b1, store hpre, accumulate BN1 stats ----
    float csum[8], csq[8];
    #pragma unroll
    for (int j = 0; j < 8; j++) { csum[j] = 0.f; csq[j] = 0.f; }
    #pragma unroll
    for (int mt = 0; mt < 4; mt++) {
        #pragma unroll
        for (int half = 0; half < 2; half++) {
            int m = m0 + warp_m * 64 + mt * 16 + half * 8 + (l >> 2);
            if (m < N_NODES) {
                #pragma unroll
                for (int nt = 0; nt < 4; nt++) {
                    int n = warp_n * 32 + nt * 8 + (l & 3) * 2;
                    float v0 = acc[mt][nt][half * 2 + 0] + __ldg(b1 + n);
                    float v1 = acc[mt][nt][half * 2 + 1] + __ldg(b1 + n + 1);
                    *(float2*)(g_hpre + (size_t)m * D + n) = make_float2(v0, v1);
                    csum[nt * 2]     += v0;  csq[nt * 2]     += v0 * v0;
                    csum[nt * 2 + 1] += v1;  csq[nt * 2 + 1] += v1 * v1;
                }
            }
        }
    }
    #pragma unroll
    for (int nt = 0; nt < 4; nt++) {
        int n = warp_n * 32 + nt * 8 + (l & 3) * 2;
        atomicAdd(&ssum[n],     csum[nt * 2]);
        atomicAdd(&ssq[n],      csq[nt * 2]);
        atomicAdd(&ssum[n + 1], csum[nt * 2 + 1]);
        atomicAdd(&ssq[n + 1],  csq[nt * 2 + 1]);
    }
    __syncthreads();
    if (tid < 128) {
        atomicAdd(&g_s1[tid], (double)ssum[tid]);
        atomicAdd(&g_q1[tid], (double)ssq[tid]);
    }
}

__global__ void k_bnparams1(const float* __restrict__ gamma1,
                            const float* __restrict__ beta1) {
    int c = threadIdx.x;
    double mu  = g_s1[c] / (double)N_NODES;
    double var = g_q1[c] / (double)N_NODES - mu * mu;
    double sc  = (double)gamma1[c] / sqrt(var + (double)BN_EPS);
    g_scale1[c] = (float)sc;
    g_shift1[c] = (float)((double)beta1[c] - mu * sc);
}

// ---------------- BN1 + ReLU + project to 2 dims (warp per node) -------------
__global__ void k_proj(const float* __restrict__ W2l, const float* __restrict__ W2r) {
    int gi = blockIdx.x * blockDim.x + threadIdx.x;
    int n    = gi >> 5;
    int lane = threadIdx.x & 31;
    if (n >= N_NODES) return;
    float4 h = *(const float4*)(g_hpre + (size_t)n * D + lane * 4);
    float hv[4] = {h.x, h.y, h.z, h.w};
    float p0 = 0.f, p1 = 0.f, r0 = 0.f, r1 = 0.f;
    #pragma unroll
    for (int j = 0; j < 4; j++) {
        int c = lane * 4 + j;
        float v = fmaxf(fmaf(hv[j], g_scale1[c], g_shift1[c]), 0.f);
        p0 = fmaf(v, W2l[2 * c],     p0);
        p1 = fmaf(v, W2l[2 * c + 1], p1);
        r0 = fmaf(v, W2r[2 * c],     r0);
        r1 = fmaf(v, W2r[2 * c + 1], r1);
    }
    #pragma unroll
    for (int o = 16; o; o >>= 1) {
        p0 += __shfl_xor_sync(0xffffffffu, p0, o);
        p1 += __shfl_xor_sync(0xffffffffu, p1, o);
        r0 += __shfl_xor_sync(0xffffffffu, r0, o);
        r1 += __shfl_xor_sync(0xffffffffu, r1, o);
    }
    if (lane == 0) {
        *(float2*)(g_p + 2 * n) = make_float2(p0, p1);
        *(float2*)(g_r + 2 * n) = make_float2(r0, r1);
    }
}

// ---------------- layer 2: CSR gather + outpre + BN2 stats (fused) ----------
__global__ void k_l2(const float* __restrict__ b2) {
    int i = blockIdx.x * blockDim.x + threadIdx.x;
    float o0 = 0.f, o1 = 0.f;
    if (i < N_NODES) {
        int beg = g_rowstart[i], end = g_rowstart[i + 1];
        float s0 = 0.f, s1 = 0.f;
        for (int e = beg; e < end; e++) {
            int sidx = __ldg(g_csr + e);
            float2 v = *(const float2*)(g_p + 2 * sidx);
            s0 += v.x; s1 += v.y;
        }
        float inv = g_inv[i];
        float2 r = *(const float2*)(g_r + 2 * i);
        o0 = fmaf(s0, inv, b2[0] + r.x);
        o1 = fmaf(s1, inv, b2[1] + r.y);
        *(float2*)(g_opre + 2 * i) = make_float2(o0, o1);
    }
    float q0 = o0 * o0, q1 = o1 * o1;
    #pragma unroll
    for (int o = 16; o; o >>= 1) {
        o0 += __shfl_xor_sync(0xffffffffu, o0, o);
        o1 += __shfl_xor_sync(0xffffffffu, o1, o);
        q0 += __shfl_xor_sync(0xffffffffu, q0, o);
        q1 += __shfl_xor_sync(0xffffffffu, q1, o);
    }
    __shared__ float sh[4][8];
    int w = threadIdx.x >> 5, ll = threadIdx.x & 31;
    if (ll == 0) { sh[0][w] = o0; sh[1][w] = o1; sh[2][w] = q0; sh[3][w] = q1; }
    __syncthreads();
    if (threadIdx.x == 0) {
        float s0 = 0.f, s1 = 0.f, t0 = 0.f, t1 = 0.f;
        #pragma unroll
        for (int k = 0; k < 8; k++) { s0 += sh[0][k]; s1 += sh[1][k]; t0 += sh[2][k]; t1 += sh[3][k]; }
        atomicAdd(&g_s2[0], (double)s0);
        atomicAdd(&g_s2[1], (double)s1);
        atomicAdd(&g_q2[0], (double)t0);
        atomicAdd(&g_q2[1], (double)t1);
    }
}

// ---------------- BN2 + log_softmax ----------------
__global__ void k_final(const float* __restrict__ gamma2, const float* __restrict__ beta2,
                        float* __restrict__ out) {
    int i = blockIdx.x * blockDim.x + threadIdx.x;
    if (i >= N_NODES) return;
    double mu0 = g_s2[0] / (double)N_NODES;
    double mu1 = g_s2[1] / (double)N_NODES;
    double v0  = g_q2[0] / (double)N_NODES - mu0 * mu0;
    double v1  = g_q2[1] / (double)N_NODES - mu1 * mu1;
    float sc0 = (float)((double)gamma2[0] / sqrt(v0 + (double)BN_EPS));
    float sc1 = (float)((double)gamma2[1] / sqrt(v1 + (double)BN_EPS));
    float sh0 = (float)((double)beta2[0] - mu0 * sc0);
    float sh1 = (float)((double)beta2[1] - mu1 * sc1);
    float2 o = *(const float2*)(g_opre + 2 * i);
    float a = fmaf(o.x, sc0, sh0);
    float b = fmaf(o.y, sc1, sh1);
    float m = fmaxf(a, b);
    float lse = m + logf(expf(a - m) + expf(b - m));
    *(float2*)(out + 2 * i) = make_float2(a - lse, b - lse);
}

// ---------------- launch ----------------
extern "C" void kernel_launch(void* const* d_in, const int* in_sizes, int n_in,
                              void* d_out, int out_size) {
    const float* x    = (const float*)d_in[0];
    const int*   ei   = (const int*)d_in[1];
    const float* W1l  = (const float*)d_in[2];
    const float* b1   = (const float*)d_in[3];
    const float* W1r  = (const float*)d_in[4];
    const float* g1   = (const float*)d_in[5];
    const float* be1  = (const float*)d_in[6];
    const float* W2l  = (const float*)d_in[7];
    const float* b2   = (const float*)d_in[8];
    const float* W2r  = (const float*)d_in[9];
    const float* g2   = (const float*)d_in[10];
    const float* be2  = (const float*)d_in[11];
    float* out = (float*)d_out;

    k_detect<<<1, 256>>>(ei);
    k_zero<<<200, 256>>>();
    k_wconv<<<128, 256>>>(W1l, W1r);
    k_hist<<<(N_EDGES + 255) / 256, 256>>>(ei);
    k_scan1<<<N_SCAN_BLKS, SCAN_BLK>>>();
    k_scan2<<<1, 128>>>();
    k_scan3<<<(N_NODES + 255) / 256, 256>>>();
    k_scatter<<<(N_EDGES + 255) / 256, 256>>>(ei);
    k_agg<<<(N_NODES * 32 + 255) / 256, 256>>>(x);
    k_gemm1<<<(N_NODES + 127) / 128, 256>>>(x, b1);
    k_bnparams1<<<1, 128>>>(g1, be1);
    k_proj<<<(N_NODES * 32 + 255) / 256, 256>>>(W2l, W2r);
    k_l2<<<(N_NODES + 255) / 256, 256>>>(b2);
    k_final<<<(N_NODES + 255) / 256, 256>>>(g2, be2, out);
}